// round 1
// baseline (speedup 1.0000x reference)
#include <cuda_runtime.h>
#include <cstdint>

// ---------------------------------------------------------------------------
// QuanvolutionHybrid: quantum patch features + conv/bn/residual + fc + logsoftmax
//
// Quantum circuit reduced to closed form (Heisenberg picture):
//   Z0 = cos(t4)cos(t0+p0) - sin(t4)sin(t0+p0)sin(p1)
//   Z1 = cos(t0+p0) cos(t1) cos(p1)
//   Z2 = Z1 * cos(p2)
//   Z3 = cos(t3) cos(p2) cos(p3)      (qw[2] provably unused)
// ---------------------------------------------------------------------------

#define MAXB 4096
#define E    784       // 4*14*14 elements per image
#define NBIN 32        // atomic contention bins for BN stats

__device__ float f_g [MAXB * E];   // quantum features (residual input)
__device__ float t1_g[MAXB * E];   // conv1 output (pre-bn)
__device__ float t2_g[MAXB * E];   // conv2 output (pre-bn)
__device__ float stats1_g[NBIN * 8];
__device__ float stats2_g[NBIN * 8];

__global__ void k_init() {
    int t = threadIdx.x;
    if (t < NBIN * 8)            stats1_g[t] = 0.f;
    else if (t < 2 * NBIN * 8)   stats2_g[t - NBIN * 8] = 0.f;
}

// Shared conv + stats epilogue: input tile in padded smem fz[4][16][16],
// weights in smem ws[4][4][3][3]. Writes dst[b*784 + oc*196 + t], accumulates
// per-channel sum/sumsq into binned global stats.
__device__ __forceinline__ void conv_stats(
    const float (&fz)[4][16][16], const float (&ws)[4][4][3][3],
    float* __restrict__ dst, float* __restrict__ stats, float* bst,
    int b, int t)
{
    float sum[4] = {0.f, 0.f, 0.f, 0.f};
    float sq [4] = {0.f, 0.f, 0.f, 0.f};
    if (t < 196) {
        int h = t / 14, w = t % 14;
        float acc[4] = {0.f, 0.f, 0.f, 0.f};
        #pragma unroll
        for (int ic = 0; ic < 4; ic++)
            #pragma unroll
            for (int kh = 0; kh < 3; kh++)
                #pragma unroll
                for (int kw = 0; kw < 3; kw++) {
                    float v = fz[ic][h + kh][w + kw];
                    #pragma unroll
                    for (int oc = 0; oc < 4; oc++)
                        acc[oc] += v * ws[oc][ic][kh][kw];
                }
        #pragma unroll
        for (int oc = 0; oc < 4; oc++) {
            dst[(size_t)b * E + oc * 196 + t] = acc[oc];
            sum[oc] = acc[oc];
            sq [oc] = acc[oc] * acc[oc];
        }
    }
    // full-block warp reduction (inactive threads contribute zeros)
    #pragma unroll
    for (int off = 16; off; off >>= 1)
        #pragma unroll
        for (int c = 0; c < 4; c++) {
            sum[c] += __shfl_down_sync(0xffffffffu, sum[c], off);
            sq [c] += __shfl_down_sync(0xffffffffu, sq [c], off);
        }
    if ((t & 31) == 0) {
        #pragma unroll
        for (int c = 0; c < 4; c++) {
            atomicAdd(&bst[c],     sum[c]);
            atomicAdd(&bst[4 + c], sq [c]);
        }
    }
    __syncthreads();
    if (t < 8) atomicAdd(&stats[(b & (NBIN - 1)) * 8 + t], bst[t]);
}

// Compute per-channel bn scale/bias from binned stats.
__device__ __forceinline__ void bn_prologue(
    const float* __restrict__ stats, const float* __restrict__ gamma,
    const float* __restrict__ beta, float* sums8, float* sc, float* bi,
    int t, float Ninv)
{
    if (t < 8) {
        float s = 0.f;
        #pragma unroll
        for (int bin = 0; bin < NBIN; bin++) s += stats[bin * 8 + t];
        sums8[t] = s;
    }
    __syncthreads();
    if (t < 4) {
        float mean = sums8[t] * Ninv;
        float var  = sums8[4 + t] * Ninv - mean * mean;
        float s    = gamma[t] * rsqrtf(var + 1e-5f);
        sc[t] = s;
        bi[t] = beta[t] - mean * s;
    }
    __syncthreads();
}

// K1: quantum features (closed form) + conv1 + stats1
__global__ void __launch_bounds__(256) k_quanv_conv1(
    const float* __restrict__ x, const float* __restrict__ qw,
    const float* __restrict__ w1)
{
    __shared__ float fz[4][16][16];
    __shared__ float ws[4][4][3][3];
    __shared__ float bst[8];
    int b = blockIdx.x, t = threadIdx.x;

    if (t < 144) (&ws[0][0][0][0])[t] = w1[t];
    if (t < 8)   bst[t] = 0.f;
    float* fzf = &fz[0][0][0];
    #pragma unroll
    for (int k = 0; k < 4; k++) fzf[t + 256 * k] = 0.f;
    __syncthreads();

    if (t < 196) {
        float t0 = qw[0], t1a = qw[1], t3 = qw[3], t4 = qw[4];
        float ct1 = __cosf(t1a), ct3 = __cosf(t3);
        float st4, ct4; __sincosf(t4, &st4, &ct4);

        int i = t / 14, j = t % 14;
        const float* xb = x + (size_t)b * E;
        float2 r0 = *reinterpret_cast<const float2*>(xb + i * 56 + j * 2);
        float2 r1 = *reinterpret_cast<const float2*>(xb + i * 56 + 28 + j * 2);
        float p0 = r0.x, p1 = r0.y, p2 = r1.x, p3 = r1.y;

        float sa, ca;   __sincosf(t0 + p0, &sa, &ca);
        float sp1, cp1; __sincosf(p1, &sp1, &cp1);
        float cp2 = __cosf(p2), cp3 = __cosf(p3);

        float m0 = ct4 * ca - st4 * sa * sp1;
        float m1 = ca * ct1 * cp1;
        float m2 = m1 * cp2;
        float m3 = ct3 * cp2 * cp3;

        // global f (residual), flat idx within batch = i*56 + j*4 + q = 4t+q
        *reinterpret_cast<float4*>(f_g + (size_t)b * E + t * 4) =
            make_float4(m0, m1, m2, m3);

        // scatter to padded NCHW smem tile (c = idx/196, r = idx%196)
        float m[4] = {m0, m1, m2, m3};
        #pragma unroll
        for (int q = 0; q < 4; q++) {
            int idx = t * 4 + q;
            int c = idx / 196, r = idx % 196;
            fz[c][r / 14 + 1][r % 14 + 1] = m[q];
        }
    }
    __syncthreads();
    conv_stats(fz, ws, t1_g, stats1_g, bst, b, t);
}

// K2: bn1 + relu + conv2 + stats2
__global__ void __launch_bounds__(256) k_conv2(
    const float* __restrict__ w2, const float* __restrict__ g1,
    const float* __restrict__ be1, int B)
{
    __shared__ float fz[4][16][16];
    __shared__ float ws[4][4][3][3];
    __shared__ float bst[8];
    __shared__ float sums8[8];
    __shared__ float sc[4], bi[4];
    int b = blockIdx.x, t = threadIdx.x;

    if (t < 144) (&ws[0][0][0][0])[t] = w2[t];
    if (t < 8)   bst[t] = 0.f;
    float* fzf = &fz[0][0][0];
    #pragma unroll
    for (int k = 0; k < 4; k++) fzf[t + 256 * k] = 0.f;
    __syncthreads();

    bn_prologue(stats1_g, g1, be1, sums8, sc, bi, t, 1.f / ((float)B * 196.f));

    #pragma unroll
    for (int k = 0; k < 4; k++) {
        int idx = t + 256 * k;
        if (idx < E) {
            float v = t1_g[(size_t)b * E + idx];
            int c = idx / 196, r = idx % 196;
            v = fmaxf(v * sc[c] + bi[c], 0.f);
            fz[c][r / 14 + 1][r % 14 + 1] = v;
        }
    }
    __syncthreads();
    conv_stats(fz, ws, t2_g, stats2_g, bst, b, t);
}

// K3: bn2 + residual + relu + fc + log_softmax
__global__ void __launch_bounds__(256) k_fc(
    const float* __restrict__ g2, const float* __restrict__ be2,
    const float* __restrict__ fcw, const float* __restrict__ fcb,
    float* __restrict__ out, int B)
{
    __shared__ float o[E];
    __shared__ float sums8[8];
    __shared__ float sc[4], bi[4];
    __shared__ float wsum[8][10];
    __shared__ float lg[10];
    int b = blockIdx.x, t = threadIdx.x;

    bn_prologue(stats2_g, g2, be2, sums8, sc, bi, t, 1.f / ((float)B * 196.f));

    #pragma unroll
    for (int k = 0; k < 4; k++) {
        int idx = t + 256 * k;
        if (idx < E) {
            int c = idx / 196;
            float v = t2_g[(size_t)b * E + idx] * sc[c] + bi[c]
                    + f_g[(size_t)b * E + idx];
            o[idx] = fmaxf(v, 0.f);
        }
    }
    __syncthreads();

    float acc[10];
    #pragma unroll
    for (int k = 0; k < 10; k++) acc[k] = 0.f;
    for (int idx = t; idx < E; idx += 256) {
        float ov = o[idx];
        #pragma unroll
        for (int k = 0; k < 10; k++)
            acc[k] += ov * __ldg(&fcw[k * E + idx]);
    }
    #pragma unroll
    for (int off = 16; off; off >>= 1)
        #pragma unroll
        for (int k = 0; k < 10; k++)
            acc[k] += __shfl_down_sync(0xffffffffu, acc[k], off);

    int warp = t >> 5, lane = t & 31;
    if (lane == 0) {
        #pragma unroll
        for (int k = 0; k < 10; k++) wsum[warp][k] = acc[k];
    }
    __syncthreads();
    if (t < 10) {
        float l = fcb[t];
        #pragma unroll
        for (int w = 0; w < 8; w++) l += wsum[w][t];
        lg[t] = l;
    }
    __syncthreads();
    if (t < 10) {
        float mx = lg[0];
        #pragma unroll
        for (int k = 1; k < 10; k++) mx = fmaxf(mx, lg[k]);
        float se = 0.f;
        #pragma unroll
        for (int k = 0; k < 10; k++) se += expf(lg[k] - mx);
        out[(size_t)b * 10 + t] = lg[t] - mx - logf(se);
    }
}

extern "C" void kernel_launch(void* const* d_in, const int* in_sizes, int n_in,
                              void* d_out, int out_size)
{
    const float* x   = (const float*)d_in[0];
    const float* qw  = (const float*)d_in[1];
    const float* w1  = (const float*)d_in[2];
    const float* g1  = (const float*)d_in[3];
    const float* be1 = (const float*)d_in[4];
    const float* w2  = (const float*)d_in[5];
    const float* g2  = (const float*)d_in[6];
    const float* be2 = (const float*)d_in[7];
    const float* fcw = (const float*)d_in[8];
    const float* fcb = (const float*)d_in[9];
    float* out = (float*)d_out;

    int B = in_sizes[0] / E;
    if (B > MAXB) B = MAXB;

    k_init<<<1, 512>>>();
    k_quanv_conv1<<<B, 256>>>(x, qw, w1);
    k_conv2<<<B, 256>>>(w2, g1, be1, B);
    k_fc<<<B, 256>>>(g2, be2, fcw, fcb, out, B);
}

// round 2
// speedup vs baseline: 1.0265x; 1.0265x over previous
#include <cuda_runtime.h>
#include <cstdint>

// ---------------------------------------------------------------------------
// QuanvolutionHybrid: closed-form quantum features + conv/bn/residual + fc.
//   Z0 = cos(t4)cos(t0+p0) - sin(t4)sin(t0+p0)sin(p1)
//   Z1 = cos(t0+p0) cos(t1) cos(p1)
//   Z2 = Z1 * cos(p2)
//   Z3 = cos(t3) cos(p2) cos(p3)      (qw[2] provably unused)
// ---------------------------------------------------------------------------

#define MAXB 4096
#define E    784
#define NBIN 32

__device__ float f_g [MAXB * E];
__device__ float t1_g[MAXB * E];
__device__ float t2_g[MAXB * E];
__device__ float stats1_g[NBIN * 8];
__device__ float stats2_g[NBIN * 8];

__global__ void k_init() {
    int t = threadIdx.x;
    if (t < NBIN * 8)            stats1_g[t] = 0.f;
    else if (t < 2 * NBIN * 8)   stats2_g[t - NBIN * 8] = 0.f;
}

// conv 3x3 (4ic->4oc) for one output pixel tt (<196) of image b from padded
// smem tile fz[4][16][16]; writes dst; then block-wide binned stats update.
__device__ __forceinline__ void conv_stats_2img(
    const float* __restrict__ fz,     // this sub-block's [4][16][16]
    const float* __restrict__ ws,     // [4][4][3][3] flat
    float* __restrict__ dst, float* __restrict__ stats,
    float* bst,                       // this sub-block's [8]
    int b, int tt, bool act)
{
    float sum[4] = {0.f, 0.f, 0.f, 0.f};
    float sq [4] = {0.f, 0.f, 0.f, 0.f};
    if (act) {
        int h = tt / 14, w = tt % 14;
        float acc[4] = {0.f, 0.f, 0.f, 0.f};
        #pragma unroll
        for (int ic = 0; ic < 4; ic++)
            #pragma unroll
            for (int kh = 0; kh < 3; kh++)
                #pragma unroll
                for (int kw = 0; kw < 3; kw++) {
                    float v = fz[(ic * 16 + h + kh) * 16 + (w + kw)];
                    #pragma unroll
                    for (int oc = 0; oc < 4; oc++)
                        acc[oc] += v * ws[((oc * 4 + ic) * 3 + kh) * 3 + kw];
                }
        #pragma unroll
        for (int oc = 0; oc < 4; oc++) {
            dst[(size_t)b * E + oc * 196 + tt] = acc[oc];
            sum[oc] = acc[oc];
            sq [oc] = acc[oc] * acc[oc];
        }
    }
    #pragma unroll
    for (int off = 16; off; off >>= 1)
        #pragma unroll
        for (int c = 0; c < 4; c++) {
            sum[c] += __shfl_down_sync(0xffffffffu, sum[c], off);
            sq [c] += __shfl_down_sync(0xffffffffu, sq [c], off);
        }
    if ((tt & 31) == 0) {
        #pragma unroll
        for (int c = 0; c < 4; c++) {
            atomicAdd(&bst[c],     sum[c]);
            atomicAdd(&bst[4 + c], sq [c]);
        }
    }
    __syncthreads();
    if (tt < 8 && act || (tt < 8 && b >= 0)) {}
    if (tt < 8) {
        // only add if this sub-block's image exists
        if (b < MAXB) atomicAdd(&stats[(b & (NBIN - 1)) * 8 + tt], bst[tt]);
    }
}

__device__ __forceinline__ void bn_prologue(
    const float* __restrict__ stats, const float* __restrict__ gamma,
    const float* __restrict__ beta, float* sums8, float* sc, float* bi,
    int t, float Ninv)
{
    if (t < 8) {
        float s = 0.f;
        #pragma unroll
        for (int bin = 0; bin < NBIN; bin++) s += stats[bin * 8 + t];
        sums8[t] = s;
    }
    __syncthreads();
    if (t < 4) {
        float mean = sums8[t] * Ninv;
        float var  = sums8[4 + t] * Ninv - mean * mean;
        float s    = gamma[t] * rsqrtf(var + 1e-5f);
        sc[t] = s;
        bi[t] = beta[t] - mean * s;
    }
    __syncthreads();
}

// K1: quantum features + conv1 + stats1.  2 images per 512-thread block.
__global__ void __launch_bounds__(512) k_quanv_conv1(
    const float* __restrict__ x, const float* __restrict__ qw,
    const float* __restrict__ w1, int B)
{
    __shared__ float fz[2][4][16][16];
    __shared__ float ws[144];
    __shared__ float bst[2][8];
    int t = threadIdx.x, sub = t >> 8, tt = t & 255;
    int b = blockIdx.x * 2 + sub;
    bool act = (tt < 196) && (b < B);

    if (t < 144) ws[t] = w1[t];
    if (tt < 8)  bst[sub][tt] = 0.f;
    float* fzf = &fz[0][0][0][0];
    #pragma unroll
    for (int k = 0; k < 4; k++) fzf[t + 512 * k] = 0.f;
    __syncthreads();

    if (act) {
        float t0 = qw[0], t1a = qw[1], t3 = qw[3], t4 = qw[4];
        float ct1 = __cosf(t1a), ct3 = __cosf(t3);
        float st4, ct4; __sincosf(t4, &st4, &ct4);

        int i = tt / 14, j = tt % 14;
        const float* xb = x + (size_t)b * E;
        float2 r0 = *reinterpret_cast<const float2*>(xb + i * 56 + j * 2);
        float2 r1 = *reinterpret_cast<const float2*>(xb + i * 56 + 28 + j * 2);
        float p0 = r0.x, p1 = r0.y, p2 = r1.x, p3 = r1.y;

        float sa, ca;   __sincosf(t0 + p0, &sa, &ca);
        float sp1, cp1; __sincosf(p1, &sp1, &cp1);
        float cp2 = __cosf(p2), cp3 = __cosf(p3);

        float m0 = ct4 * ca - st4 * sa * sp1;
        float m1 = ca * ct1 * cp1;
        float m2 = m1 * cp2;
        float m3 = ct3 * cp2 * cp3;

        *reinterpret_cast<float4*>(f_g + (size_t)b * E + tt * 4) =
            make_float4(m0, m1, m2, m3);

        float m[4] = {m0, m1, m2, m3};
        #pragma unroll
        for (int q = 0; q < 4; q++) {
            int idx = tt * 4 + q;
            int c = idx / 196, r = idx % 196;
            fz[sub][c][r / 14 + 1][r % 14 + 1] = m[q];
        }
    }
    __syncthreads();

    if (b >= B) b = MAXB;  // disable final stats atomic for ghost image
    conv_stats_2img(&fz[sub][0][0][0], ws, t1_g, stats1_g, bst[sub], b, tt, act);
}

// K2: bn1 + relu + conv2 + stats2.  2 images per 512-thread block.
__global__ void __launch_bounds__(512) k_conv2(
    const float* __restrict__ w2, const float* __restrict__ g1,
    const float* __restrict__ be1, int B)
{
    __shared__ float fz[2][4][16][16];
    __shared__ float ws[144];
    __shared__ float bst[2][8];
    __shared__ float sums8[8];
    __shared__ float sc[4], bi[4];
    int t = threadIdx.x, sub = t >> 8, tt = t & 255;
    int b = blockIdx.x * 2 + sub;
    bool act = (tt < 196) && (b < B);

    if (t < 144) ws[t] = w2[t];
    if (tt < 8)  bst[sub][tt] = 0.f;
    float* fzf = &fz[0][0][0][0];
    #pragma unroll
    for (int k = 0; k < 4; k++) fzf[t + 512 * k] = 0.f;
    __syncthreads();

    bn_prologue(stats1_g, g1, be1, sums8, sc, bi, t, 1.f / ((float)B * 196.f));

    #pragma unroll
    for (int k = 0; k < 4; k++) {
        int idx = tt + 256 * k;
        if (idx < E && b < B) {
            float v = t1_g[(size_t)b * E + idx];
            int c = idx / 196, r = idx % 196;
            v = fmaxf(v * sc[c] + bi[c], 0.f);
            fz[sub][c][r / 14 + 1][r % 14 + 1] = v;
        }
    }
    __syncthreads();

    int bb = (b < B) ? b : MAXB;
    conv_stats_2img(&fz[sub][0][0][0], ws, t2_g, stats2_g, bst[sub], bb, tt, act);
}

// K3: bn2 + residual + relu + fc + log_softmax.  8 images (1/warp) per block,
// fc_w staged in shared memory once per block.
__global__ void __launch_bounds__(256) k_fc(
    const float* __restrict__ g2, const float* __restrict__ be2,
    const float* __restrict__ fcw, const float* __restrict__ fcb,
    float* __restrict__ out, int B)
{
    __shared__ float fcw_s[7840];
    __shared__ float sums8[8];
    __shared__ float sc[4], bi[4];
    __shared__ float fcb_s[10];
    int t = threadIdx.x;

    bn_prologue(stats2_g, g2, be2, sums8, sc, bi, t, 1.f / ((float)B * 196.f));

    if (t < 10) fcb_s[t] = fcb[t];
    for (int i = t; i < 7840; i += 256) fcw_s[i] = __ldg(&fcw[i]);
    __syncthreads();

    int warp = t >> 5, lane = t & 31;
    int b = blockIdx.x * 8 + warp;
    if (b >= B) return;

    float acc[10];
    #pragma unroll
    for (int k = 0; k < 10; k++) acc[k] = 0.f;

    const float* t2b = t2_g + (size_t)b * E;
    const float* fb  = f_g  + (size_t)b * E;
    for (int idx = lane; idx < E; idx += 32) {
        int c = idx / 196;
        float v = t2b[idx] * sc[c] + bi[c] + fb[idx];
        v = fmaxf(v, 0.f);
        #pragma unroll
        for (int k = 0; k < 10; k++)
            acc[k] += v * fcw_s[k * E + idx];
    }
    #pragma unroll
    for (int off = 16; off; off >>= 1)
        #pragma unroll
        for (int k = 0; k < 10; k++)
            acc[k] += __shfl_down_sync(0xffffffffu, acc[k], off);

    if (lane == 0) {
        float lg[10];
        float mx = -1e30f;
        #pragma unroll
        for (int k = 0; k < 10; k++) {
            lg[k] = acc[k] + fcb_s[k];
            mx = fmaxf(mx, lg[k]);
        }
        float se = 0.f;
        #pragma unroll
        for (int k = 0; k < 10; k++) se += expf(lg[k] - mx);
        float lse = mx + logf(se);
        #pragma unroll
        for (int k = 0; k < 10; k++)
            out[(size_t)b * 10 + k] = lg[k] - lse;
    }
}

extern "C" void kernel_launch(void* const* d_in, const int* in_sizes, int n_in,
                              void* d_out, int out_size)
{
    const float* x   = (const float*)d_in[0];
    const float* qw  = (const float*)d_in[1];
    const float* w1  = (const float*)d_in[2];
    const float* g1  = (const float*)d_in[3];
    const float* be1 = (const float*)d_in[4];
    const float* w2  = (const float*)d_in[5];
    const float* g2  = (const float*)d_in[6];
    const float* be2 = (const float*)d_in[7];
    const float* fcw = (const float*)d_in[8];
    const float* fcb = (const float*)d_in[9];
    float* out = (float*)d_out;

    int B = in_sizes[0] / E;
    if (B > MAXB) B = MAXB;

    k_init<<<1, 512>>>();
    k_quanv_conv1<<<(B + 1) / 2, 512>>>(x, qw, w1, B);
    k_conv2<<<(B + 1) / 2, 512>>>(w2, g1, be1, B);
    k_fc<<<(B + 7) / 8, 256>>>(g2, be2, fcw, fcb, out, B);
}

// round 3
// speedup vs baseline: 1.4812x; 1.4430x over previous
#include <cuda_runtime.h>
#include <cstdint>

// ---------------------------------------------------------------------------
// QuanvolutionHybrid: closed-form quantum features + conv/bn/residual + fc.
//   Z0 = cos(t4)cos(t0+p0) - sin(t4)sin(t0+p0)sin(p1)
//   Z1 = cos(t0+p0) cos(t1) cos(p1)
//   Z2 = Z1 * cos(p2)
//   Z3 = cos(t3) cos(p2) cos(p3)      (qw[2] provably unused)
// ---------------------------------------------------------------------------

#define MAXB 4096
#define E    784
#define NBIN 32

__device__ float f_g [MAXB * E];
__device__ float t1_g[MAXB * E];
__device__ float t2_g[MAXB * E];
__device__ float stats1_g[NBIN * 8];
__device__ float stats2_g[NBIN * 8];

__global__ void k_init() {
    int t = threadIdx.x;
    if (t < NBIN * 8)            stats1_g[t] = 0.f;
    else if (t < 2 * NBIN * 8)   stats2_g[t - NBIN * 8] = 0.f;
}

// Stage weights transposed: wt[((ic*3+kh)*3+kw)*4+oc] from w[((oc*4+ic)*3+kh)*3+kw]
__device__ __forceinline__ void stage_weights(const float* __restrict__ w,
                                              float* wt, int t) {
    if (t < 144) {
        int oc = t & 3, rest = t >> 2;
        int kw = rest % 3, kh = (rest / 3) % 3, ic = rest / 9;
        wt[t] = w[((oc * 4 + ic) * 3 + kh) * 3 + kw];
    }
}

// Conv 3x3 (4ic->4oc), 2 output pixels per thread, from padded tile
// fz[4][16][16] (data at [1..14][1..14]).  r<98: h=r/7, w0=2*(r%7).
// Then per-image stats reduction into binned global accumulators.
__device__ __forceinline__ void conv2pix_stats(
    const float* __restrict__ fz, const float* __restrict__ wt,
    float* __restrict__ dst, float* __restrict__ stats,
    float* bst8,                 // this image's smem [8]
    int b, int r, bool act)
{
    float acc[4][2] = {{0.f,0.f},{0.f,0.f},{0.f,0.f},{0.f,0.f}};
    if (act) {
        int h = r / 7, w0 = (r % 7) * 2;
        #pragma unroll
        for (int ic = 0; ic < 4; ic++)
            #pragma unroll
            for (int kh = 0; kh < 3; kh++) {
                const float* row = fz + (ic * 16 + h + kh) * 16 + w0;
                float2 A = *reinterpret_cast<const float2*>(row);
                float2 Bv = *reinterpret_cast<const float2*>(row + 2);
                float a0 = A.x, a1 = A.y, a2 = Bv.x, a3 = Bv.y;
                const float* wrow = wt + (ic * 3 + kh) * 12;
                float4 w0v = *reinterpret_cast<const float4*>(wrow);
                float4 w1v = *reinterpret_cast<const float4*>(wrow + 4);
                float4 w2v = *reinterpret_cast<const float4*>(wrow + 8);
                acc[0][0] += a0*w0v.x; acc[0][1] += a1*w0v.x;
                acc[1][0] += a0*w0v.y; acc[1][1] += a1*w0v.y;
                acc[2][0] += a0*w0v.z; acc[2][1] += a1*w0v.z;
                acc[3][0] += a0*w0v.w; acc[3][1] += a1*w0v.w;
                acc[0][0] += a1*w1v.x; acc[0][1] += a2*w1v.x;
                acc[1][0] += a1*w1v.y; acc[1][1] += a2*w1v.y;
                acc[2][0] += a1*w1v.z; acc[2][1] += a2*w1v.z;
                acc[3][0] += a1*w1v.w; acc[3][1] += a2*w1v.w;
                acc[0][0] += a2*w2v.x; acc[0][1] += a3*w2v.x;
                acc[1][0] += a2*w2v.y; acc[1][1] += a3*w2v.y;
                acc[2][0] += a2*w2v.z; acc[2][1] += a3*w2v.z;
                acc[3][0] += a2*w2v.w; acc[3][1] += a3*w2v.w;
            }
        int base = (int)((size_t)b * E) + h * 14 + w0;
        #pragma unroll
        for (int oc = 0; oc < 4; oc++)
            *reinterpret_cast<float2*>(dst + base + oc * 196) =
                make_float2(acc[oc][0], acc[oc][1]);
    }
    float s[8];
    #pragma unroll
    for (int c = 0; c < 4; c++) {
        s[c]     = acc[c][0] + acc[c][1];
        s[4 + c] = acc[c][0]*acc[c][0] + acc[c][1]*acc[c][1];
    }
    #pragma unroll
    for (int off = 16; off; off >>= 1)
        #pragma unroll
        for (int c = 0; c < 8; c++)
            s[c] += __shfl_down_sync(0xffffffffu, s[c], off);
    if ((r & 31) == 0) {
        #pragma unroll
        for (int c = 0; c < 8; c++) atomicAdd(&bst8[c], s[c]);
    }
    __syncthreads();
    if (r < 8 && b < MAXB)
        atomicAdd(&stats[(b & (NBIN - 1)) * 8 + r], bst8[r]);
}

__device__ __forceinline__ void bn_prologue(
    const float* __restrict__ stats, const float* __restrict__ gamma,
    const float* __restrict__ beta, float* sums8, float* sc, float* bi,
    int t, float Ninv)
{
    if (t < 8) {
        float s = 0.f;
        #pragma unroll
        for (int bin = 0; bin < NBIN; bin++) s += stats[bin * 8 + t];
        sums8[t] = s;
    }
    __syncthreads();
    if (t < 4) {
        float mean = sums8[t] * Ninv;
        float var  = sums8[4 + t] * Ninv - mean * mean;
        float s    = gamma[t] * rsqrtf(var + 1e-5f);
        sc[t] = s;
        bi[t] = beta[t] - mean * s;
    }
    __syncthreads();
}

// K1: quantum features + conv1 + stats1.  2 images / 256-thread block.
__global__ void __launch_bounds__(256) k_quanv_conv1(
    const float* __restrict__ x, const float* __restrict__ qw,
    const float* __restrict__ w1, int B)
{
    __shared__ float fz[2][4][16][16];
    __shared__ float wt[144];
    __shared__ float bst[2][8];
    int t = threadIdx.x, img = t >> 7, r = t & 127;
    int b = blockIdx.x * 2 + img;

    stage_weights(w1, wt, t);
    if (r < 8) bst[img][r] = 0.f;
    float* fzf = &fz[0][0][0][0];
    #pragma unroll
    for (int k = 0; k < 8; k++) fzf[t + 256 * k] = 0.f;
    __syncthreads();

    float t0 = qw[0], t1a = qw[1], t3 = qw[3], t4 = qw[4];
    float ct1 = __cosf(t1a), ct3 = __cosf(t3);
    float st4, ct4; __sincosf(t4, &st4, &ct4);

    int b0 = blockIdx.x * 2;
    for (int idx = t; idx < 392; idx += 256) {
        int im = idx / 196, pp = idx % 196;
        int bb = b0 + im;
        if (bb >= B) break;
        int i = pp / 14, j = pp % 14;
        const float* xb = x + (size_t)bb * E;
        float2 r0 = *reinterpret_cast<const float2*>(xb + i * 56 + j * 2);
        float2 r1 = *reinterpret_cast<const float2*>(xb + i * 56 + 28 + j * 2);
        float sa, ca;   __sincosf(t0 + r0.x, &sa, &ca);
        float sp1, cp1; __sincosf(r0.y, &sp1, &cp1);
        float cp2 = __cosf(r1.x), cp3 = __cosf(r1.y);

        float m0 = ct4 * ca - st4 * sa * sp1;
        float m1 = ca * ct1 * cp1;
        float m2 = m1 * cp2;
        float m3 = ct3 * cp2 * cp3;

        *reinterpret_cast<float4*>(f_g + (size_t)bb * E + pp * 4) =
            make_float4(m0, m1, m2, m3);

        float m[4] = {m0, m1, m2, m3};
        #pragma unroll
        for (int q = 0; q < 4; q++) {
            int e = pp * 4 + q;
            int c = e / 196, rr = e % 196;
            fz[im][c][rr / 14 + 1][rr % 14 + 1] = m[q];
        }
    }
    __syncthreads();

    bool act = (r < 98) && (b < B);
    conv2pix_stats(&fz[img][0][0][0], wt, t1_g, stats1_g, bst[img],
                   (b < B) ? b : MAXB, r, act);
}

// K2: bn1 + relu + conv2 + stats2.  2 images / 256-thread block.
__global__ void __launch_bounds__(256) k_conv2(
    const float* __restrict__ w2, const float* __restrict__ g1,
    const float* __restrict__ be1, int B)
{
    __shared__ float fz[2][4][16][16];
    __shared__ float wt[144];
    __shared__ float bst[2][8];
    __shared__ float sums8[8];
    __shared__ float sc[4], bi[4];
    int t = threadIdx.x, img = t >> 7, r = t & 127;
    int b = blockIdx.x * 2 + img;

    stage_weights(w2, wt, t);
    if (r < 8) bst[img][r] = 0.f;
    float* fzf = &fz[0][0][0][0];
    #pragma unroll
    for (int k = 0; k < 8; k++) fzf[t + 256 * k] = 0.f;
    __syncthreads();

    bn_prologue(stats1_g, g1, be1, sums8, sc, bi, t, 1.f / ((float)B * 196.f));

    int b0 = blockIdx.x * 2;
    for (int i4 = t; i4 < 392; i4 += 256) {
        int im = i4 / 196, e4 = i4 % 196;
        int bb = b0 + im;
        if (bb >= B) break;
        float4 v = *reinterpret_cast<const float4*>(t1_g + (size_t)bb * E + e4 * 4);
        int c = e4 / 49;               // 4 elements share one channel (196%4==0)
        float s = sc[c], o = bi[c];
        float vv[4] = { fmaxf(v.x*s+o, 0.f), fmaxf(v.y*s+o, 0.f),
                        fmaxf(v.z*s+o, 0.f), fmaxf(v.w*s+o, 0.f) };
        int rr = (e4 * 4) % 196;
        #pragma unroll
        for (int q = 0; q < 4; q++) {
            int rq = rr + q;
            fz[im][c][rq / 14 + 1][rq % 14 + 1] = vv[q];
        }
    }
    __syncthreads();

    bool act = (r < 98) && (b < B);
    conv2pix_stats(&fz[img][0][0][0], wt, t2_g, stats2_g, bst[img],
                   (b < B) ? b : MAXB, r, act);
}

// K3: bn2 + residual + relu + fc + log_softmax.  8 images (1/warp) / block,
// fcw staged once per block as float4.
__global__ void __launch_bounds__(256) k_fc(
    const float* __restrict__ g2, const float* __restrict__ be2,
    const float* __restrict__ fcw, const float* __restrict__ fcb,
    float* __restrict__ out, int B)
{
    __shared__ float4 fcw_s[1960];     // [10][196]
    __shared__ float sums8[8];
    __shared__ float sc[4], bi[4];
    __shared__ float fcb_s[10];
    int t = threadIdx.x;

    bn_prologue(stats2_g, g2, be2, sums8, sc, bi, t, 1.f / ((float)B * 196.f));

    if (t < 10) fcb_s[t] = fcb[t];
    const float4* fcw4 = reinterpret_cast<const float4*>(fcw);
    for (int i = t; i < 1960; i += 256) fcw_s[i] = __ldg(&fcw4[i]);
    __syncthreads();

    int warp = t >> 5, lane = t & 31;
    int b = blockIdx.x * 8 + warp;
    if (b >= B) return;

    float acc[10];
    #pragma unroll
    for (int k = 0; k < 10; k++) acc[k] = 0.f;

    const float4* t2b = reinterpret_cast<const float4*>(t2_g + (size_t)b * E);
    const float4* fb  = reinterpret_cast<const float4*>(f_g  + (size_t)b * E);
    for (int i = lane; i < 196; i += 32) {
        float4 v = t2b[i], fv = fb[i];
        int c = i / 49;
        float s = sc[c], o = bi[c];
        float v0 = fmaxf(v.x*s+o+fv.x, 0.f);
        float v1 = fmaxf(v.y*s+o+fv.y, 0.f);
        float v2 = fmaxf(v.z*s+o+fv.z, 0.f);
        float v3 = fmaxf(v.w*s+o+fv.w, 0.f);
        #pragma unroll
        for (int k = 0; k < 10; k++) {
            float4 w = fcw_s[k * 196 + i];
            acc[k] += v0*w.x + v1*w.y + v2*w.z + v3*w.w;
        }
    }
    #pragma unroll
    for (int off = 16; off; off >>= 1)
        #pragma unroll
        for (int k = 0; k < 10; k++)
            acc[k] += __shfl_down_sync(0xffffffffu, acc[k], off);

    if (lane == 0) {
        float lg[10];
        float mx = -1e30f;
        #pragma unroll
        for (int k = 0; k < 10; k++) {
            lg[k] = acc[k] + fcb_s[k];
            mx = fmaxf(mx, lg[k]);
        }
        float se = 0.f;
        #pragma unroll
        for (int k = 0; k < 10; k++) se += expf(lg[k] - mx);
        float lse = mx + logf(se);
        #pragma unroll
        for (int k = 0; k < 10; k++)
            out[(size_t)b * 10 + k] = lg[k] - lse;
    }
}

extern "C" void kernel_launch(void* const* d_in, const int* in_sizes, int n_in,
                              void* d_out, int out_size)
{
    const float* x   = (const float*)d_in[0];
    const float* qw  = (const float*)d_in[1];
    const float* w1  = (const float*)d_in[2];
    const float* g1  = (const float*)d_in[3];
    const float* be1 = (const float*)d_in[4];
    const float* w2  = (const float*)d_in[5];
    const float* g2  = (const float*)d_in[6];
    const float* be2 = (const float*)d_in[7];
    const float* fcw = (const float*)d_in[8];
    const float* fcb = (const float*)d_in[9];
    float* out = (float*)d_out;

    int B = in_sizes[0] / E;
    if (B > MAXB) B = MAXB;

    k_init<<<1, 512>>>();
    k_quanv_conv1<<<(B + 1) / 2, 256>>>(x, qw, w1, B);
    k_conv2<<<(B + 1) / 2, 256>>>(w2, g1, be1, B);
    k_fc<<<(B + 7) / 8, 256>>>(g2, be2, fcw, fcb, out, B);
}

// round 4
// speedup vs baseline: 1.4829x; 1.0012x over previous
#include <cuda_runtime.h>
#include <cstdint>

// ---------------------------------------------------------------------------
// QuanvolutionHybrid: closed-form quantum features + conv/bn/residual + fc.
//   Z0 = cos(t4)cos(t0+p0) - sin(t4)sin(t0+p0)sin(p1)
//   Z1 = cos(t0+p0) cos(t1) cos(p1)
//   Z2 = Z1 * cos(p2)
//   Z3 = cos(t3) cos(p2) cos(p3)      (qw[2] provably unused)
// One warp per image; packed f32x2 FMAs.
// ---------------------------------------------------------------------------

#define MAXB 4096
#define E    784
#define NBIN 32
#define FST  17              // fz row stride (floats) -> <=2-way LDS conflicts
#define FIMG (4 * 16 * FST)  // 1088 floats per image tile

typedef unsigned long long u64;

__device__ float f_g [MAXB * E];
__device__ float t1_g[MAXB * E];
__device__ float t2_g[MAXB * E];
__device__ float stats1_g[NBIN * 8];
__device__ float stats2_g[NBIN * 8];

__device__ __forceinline__ u64 fma2(u64 a, u64 b, u64 c) {
    u64 d;
    asm("fma.rn.f32x2 %0, %1, %2, %3;" : "=l"(d) : "l"(a), "l"(b), "l"(c));
    return d;
}
__device__ __forceinline__ u64 pack2(float lo, float hi) {
    u64 d;
    asm("mov.b64 %0, {%1, %2};" : "=l"(d) : "f"(lo), "f"(hi));
    return d;
}
__device__ __forceinline__ float2 unpack2(u64 v) {
    float lo, hi;
    asm("mov.b64 {%0, %1}, %2;" : "=f"(lo), "=f"(hi) : "l"(v));
    return make_float2(lo, hi);
}

__global__ void k_init() {
    int t = threadIdx.x;
    if (t < NBIN * 8)            stats1_g[t] = 0.f;
    else if (t < 2 * NBIN * 8)   stats2_g[t - NBIN * 8] = 0.f;
}

// Stage conv weights transposed + duplicated: pair i=(ic*3+kh)*12+kw*4+oc holds
// (w,w) at wt2[2i], wt2[2i+1].
__device__ __forceinline__ void stage_weights(const float* __restrict__ w,
                                              float* wt2, int t, int nthr) {
    for (int i = t; i < 144; i += nthr) {
        int oc = i & 3, rest = i >> 2;
        int kw = rest % 3, kh = (rest / 3) % 3, ic = rest / 9;
        float v = w[((oc * 4 + ic) * 3 + kh) * 3 + kw];
        wt2[2 * i] = v;
        wt2[2 * i + 1] = v;
    }
}

// Warp-synchronous conv 3x3 (4ic->4oc) on one image tile. Lane l<28 handles
// half-row: row=l>>1, w0=(l&1)*7 (7 output pixels). Pixel pairs via f32x2;
// the 4th pair's hi lane is garbage (discarded). Stats: warp reduce + 8 REDG.
__device__ __forceinline__ void warp_conv_stats(
    const float* __restrict__ myfz, const float* __restrict__ wt2,
    float* __restrict__ dst_img, float* __restrict__ stats, int b, int lane)
{
    float s[8] = {0.f, 0.f, 0.f, 0.f, 0.f, 0.f, 0.f, 0.f};
    if (lane < 28) {
        int row = lane >> 1, w0 = (lane & 1) * 7;
        u64 acc[4][4];
        #pragma unroll
        for (int oc = 0; oc < 4; oc++) {
            #pragma unroll
            for (int p = 0; p < 4; p++) acc[oc][p] = 0ull;
        }
        #pragma unroll
        for (int ic = 0; ic < 4; ic++) {
            #pragma unroll
            for (int kh = 0; kh < 3; kh++) {
                const float* rp = myfz + (ic * 16 + row + kh) * FST + w0;
                float a[10];
                #pragma unroll
                for (int q = 0; q < 10; q++) a[q] = rp[q];
                u64 P[9];
                #pragma unroll
                for (int q = 0; q < 9; q++) P[q] = pack2(a[q], a[q + 1]);
                const ulonglong2* wp =
                    reinterpret_cast<const ulonglong2*>(wt2) + (ic * 3 + kh) * 6;
                #pragma unroll
                for (int kw = 0; kw < 3; kw++) {
                    ulonglong2 wA = wp[kw * 2];      // oc0, oc1
                    ulonglong2 wB = wp[kw * 2 + 1];  // oc2, oc3
                    acc[0][0] = fma2(P[kw],     wA.x, acc[0][0]);
                    acc[0][1] = fma2(P[2 + kw], wA.x, acc[0][1]);
                    acc[0][2] = fma2(P[4 + kw], wA.x, acc[0][2]);
                    acc[0][3] = fma2(P[6 + kw], wA.x, acc[0][3]);
                    acc[1][0] = fma2(P[kw],     wA.y, acc[1][0]);
                    acc[1][1] = fma2(P[2 + kw], wA.y, acc[1][1]);
                    acc[1][2] = fma2(P[4 + kw], wA.y, acc[1][2]);
                    acc[1][3] = fma2(P[6 + kw], wA.y, acc[1][3]);
                    acc[2][0] = fma2(P[kw],     wB.x, acc[2][0]);
                    acc[2][1] = fma2(P[2 + kw], wB.x, acc[2][1]);
                    acc[2][2] = fma2(P[4 + kw], wB.x, acc[2][2]);
                    acc[2][3] = fma2(P[6 + kw], wB.x, acc[2][3]);
                    acc[3][0] = fma2(P[kw],     wB.y, acc[3][0]);
                    acc[3][1] = fma2(P[2 + kw], wB.y, acc[3][1]);
                    acc[3][2] = fma2(P[4 + kw], wB.y, acc[3][2]);
                    acc[3][3] = fma2(P[6 + kw], wB.y, acc[3][3]);
                }
            }
        }
        int base = row * 14 + w0;
        #pragma unroll
        for (int oc = 0; oc < 4; oc++) {
            float2 u0 = unpack2(acc[oc][0]);
            float2 u1 = unpack2(acc[oc][1]);
            float2 u2 = unpack2(acc[oc][2]);
            float2 u3 = unpack2(acc[oc][3]);     // .y is garbage (px 7)
            float v[7] = {u0.x, u0.y, u1.x, u1.y, u2.x, u2.y, u3.x};
            float* dp = dst_img + oc * 196 + base;
            #pragma unroll
            for (int j = 0; j < 7; j++) {
                dp[j] = v[j];
                s[oc]     += v[j];
                s[4 + oc] += v[j] * v[j];
            }
        }
    }
    #pragma unroll
    for (int off = 16; off; off >>= 1) {
        #pragma unroll
        for (int c = 0; c < 8; c++)
            s[c] += __shfl_down_sync(0xffffffffu, s[c], off);
    }
    if (lane == 0) {
        #pragma unroll
        for (int c = 0; c < 8; c++)
            atomicAdd(&stats[(b & (NBIN - 1)) * 8 + c], s[c]);
    }
}

__device__ __forceinline__ void bn_prologue(
    const float* __restrict__ stats, const float* __restrict__ gamma,
    const float* __restrict__ beta, float* sums8, float* sc, float* bi,
    int t, float Ninv)
{
    if (t < 8) {
        float s = 0.f;
        #pragma unroll
        for (int bin = 0; bin < NBIN; bin++) s += stats[bin * 8 + t];
        sums8[t] = s;
    }
    __syncthreads();
    if (t < 4) {
        float mean = sums8[t] * Ninv;
        float var  = sums8[4 + t] * Ninv - mean * mean;
        float s    = gamma[t] * rsqrtf(var + 1e-5f);
        sc[t] = s;
        bi[t] = beta[t] - mean * s;
    }
    __syncthreads();
}

// K1: quantum features + conv1 + stats1.  1 warp/image, 4 images/block.
__global__ void __launch_bounds__(128) k_quanv_conv1(
    const float* __restrict__ x, const float* __restrict__ qw,
    const float* __restrict__ w1, int B)
{
    __shared__ __align__(16) float fz[4 * FIMG];
    __shared__ __align__(16) float wt2[288];
    int t = threadIdx.x, warp = t >> 5, lane = t & 31;
    int b = blockIdx.x * 4 + warp;

    stage_weights(w1, wt2, t, 128);
    float* myfz = fz + warp * FIMG;
    float4* mz = reinterpret_cast<float4*>(myfz);
    #pragma unroll
    for (int i = lane; i < FIMG / 4; i += 32)
        mz[i] = make_float4(0.f, 0.f, 0.f, 0.f);
    __syncthreads();
    if (b >= B) return;

    float t0 = qw[0], t1a = qw[1], t3 = qw[3], t4 = qw[4];
    float ct1 = __cosf(t1a), ct3 = __cosf(t3);
    float st4, ct4; __sincosf(t4, &st4, &ct4);

    const float* xb = x + (size_t)b * E;
    #pragma unroll
    for (int it = 0; it < 7; it++) {
        int p = it * 32 + lane;
        if (p < 196) {
            int i = p / 14, j = p % 14;
            float2 r0 = *reinterpret_cast<const float2*>(xb + i * 56 + j * 2);
            float2 r1 = *reinterpret_cast<const float2*>(xb + i * 56 + 28 + j * 2);
            float sa, ca;   __sincosf(t0 + r0.x, &sa, &ca);
            float sp1, cp1; __sincosf(r0.y, &sp1, &cp1);
            float cp2 = __cosf(r1.x), cp3 = __cosf(r1.y);

            float m0 = ct4 * ca - st4 * sa * sp1;
            float m1 = ca * ct1 * cp1;
            float m2 = m1 * cp2;
            float m3 = ct3 * cp2 * cp3;

            *reinterpret_cast<float4*>(f_g + (size_t)b * E + p * 4) =
                make_float4(m0, m1, m2, m3);

            float m[4] = {m0, m1, m2, m3};
            #pragma unroll
            for (int q = 0; q < 4; q++) {
                int e = p * 4 + q, c = e / 196, rr = e % 196;
                myfz[(c * 16 + rr / 14 + 1) * FST + rr % 14 + 1] = m[q];
            }
        }
    }
    __syncwarp();
    warp_conv_stats(myfz, wt2, t1_g + (size_t)b * E, stats1_g, b, lane);
}

// K2: bn1 + relu + conv2 + stats2.  1 warp/image, 4 images/block.
__global__ void __launch_bounds__(128) k_conv2(
    const float* __restrict__ w2, const float* __restrict__ g1,
    const float* __restrict__ be1, int B)
{
    __shared__ __align__(16) float fz[4 * FIMG];
    __shared__ __align__(16) float wt2[288];
    __shared__ float sums8[8], sc[4], bi[4];
    int t = threadIdx.x, warp = t >> 5, lane = t & 31;
    int b = blockIdx.x * 4 + warp;

    stage_weights(w2, wt2, t, 128);
    float* myfz = fz + warp * FIMG;
    float4* mz = reinterpret_cast<float4*>(myfz);
    #pragma unroll
    for (int i = lane; i < FIMG / 4; i += 32)
        mz[i] = make_float4(0.f, 0.f, 0.f, 0.f);

    bn_prologue(stats1_g, g1, be1, sums8, sc, bi, t, 1.f / ((float)B * 196.f));
    if (b >= B) return;

    #pragma unroll
    for (int it = 0; it < 7; it++) {
        int e4 = it * 32 + lane;
        if (e4 < 196) {
            float4 v = *reinterpret_cast<const float4*>(
                t1_g + (size_t)b * E + e4 * 4);
            int c = e4 / 49;
            float s = sc[c], o = bi[c];
            float vv[4] = { fmaxf(v.x * s + o, 0.f), fmaxf(v.y * s + o, 0.f),
                            fmaxf(v.z * s + o, 0.f), fmaxf(v.w * s + o, 0.f) };
            int rr = (e4 * 4) % 196;
            #pragma unroll
            for (int q = 0; q < 4; q++) {
                int rq = rr + q;
                myfz[(c * 16 + rq / 14 + 1) * FST + rq % 14 + 1] = vv[q];
            }
        }
    }
    __syncwarp();
    warp_conv_stats(myfz, wt2, t2_g + (size_t)b * E, stats2_g, b, lane);
}

// K3: bn2 + residual + relu + fc + log_softmax.  1 warp/image, 16 images/block.
__global__ void __launch_bounds__(512) k_fc(
    const float* __restrict__ g2, const float* __restrict__ be2,
    const float* __restrict__ fcw, const float* __restrict__ fcb,
    float* __restrict__ out, int B)
{
    __shared__ __align__(16) float4 fcw_s[1960];   // [10][196] float4
    __shared__ float sums8[8], sc[4], bi[4], fcb_s[10];
    int t = threadIdx.x, warp = t >> 5, lane = t & 31;

    bn_prologue(stats2_g, g2, be2, sums8, sc, bi, t, 1.f / ((float)B * 196.f));

    if (t < 10) fcb_s[t] = fcb[t];
    const float4* f4 = reinterpret_cast<const float4*>(fcw);
    for (int i = t; i < 1960; i += 512) fcw_s[i] = __ldg(&f4[i]);
    __syncthreads();

    int b = blockIdx.x * 16 + warp;
    if (b >= B) return;

    u64 acc[10];
    #pragma unroll
    for (int k = 0; k < 10; k++) acc[k] = 0ull;

    const float4* t2b = reinterpret_cast<const float4*>(t2_g + (size_t)b * E);
    const float4* fb  = reinterpret_cast<const float4*>(f_g  + (size_t)b * E);
    const ulonglong2* fw = reinterpret_cast<const ulonglong2*>(fcw_s);
    #pragma unroll
    for (int it = 0; it < 7; it++) {
        int i = it * 32 + lane;
        if (i < 196) {
            float4 v = t2b[i], fv = fb[i];
            int c = i / 49;
            float s = sc[c], o = bi[c];
            u64 A  = pack2(fmaxf(v.x * s + o + fv.x, 0.f),
                           fmaxf(v.y * s + o + fv.y, 0.f));
            u64 Bp = pack2(fmaxf(v.z * s + o + fv.z, 0.f),
                           fmaxf(v.w * s + o + fv.w, 0.f));
            #pragma unroll
            for (int k = 0; k < 10; k++) {
                ulonglong2 w = fw[k * 196 + i];
                acc[k] = fma2(A,  w.x, acc[k]);
                acc[k] = fma2(Bp, w.y, acc[k]);
            }
        }
    }
    float accs[10];
    #pragma unroll
    for (int k = 0; k < 10; k++) {
        float2 u = unpack2(acc[k]);
        accs[k] = u.x + u.y;
    }
    #pragma unroll
    for (int off = 16; off; off >>= 1) {
        #pragma unroll
        for (int k = 0; k < 10; k++)
            accs[k] += __shfl_down_sync(0xffffffffu, accs[k], off);
    }
    if (lane == 0) {
        float lg[10], mx = -1e30f;
        #pragma unroll
        for (int k = 0; k < 10; k++) {
            lg[k] = accs[k] + fcb_s[k];
            mx = fmaxf(mx, lg[k]);
        }
        float se = 0.f;
        #pragma unroll
        for (int k = 0; k < 10; k++) se += expf(lg[k] - mx);
        float lse = mx + logf(se);
        #pragma unroll
        for (int k = 0; k < 10; k++)
            out[(size_t)b * 10 + k] = lg[k] - lse;
    }
}

extern "C" void kernel_launch(void* const* d_in, const int* in_sizes, int n_in,
                              void* d_out, int out_size)
{
    const float* x   = (const float*)d_in[0];
    const float* qw  = (const float*)d_in[1];
    const float* w1  = (const float*)d_in[2];
    const float* g1  = (const float*)d_in[3];
    const float* be1 = (const float*)d_in[4];
    const float* w2  = (const float*)d_in[5];
    const float* g2  = (const float*)d_in[6];
    const float* be2 = (const float*)d_in[7];
    const float* fcw = (const float*)d_in[8];
    const float* fcb = (const float*)d_in[9];
    float* out = (float*)d_out;

    int B = in_sizes[0] / E;
    if (B > MAXB) B = MAXB;

    k_init<<<1, 512>>>();
    k_quanv_conv1<<<(B + 3) / 4, 128>>>(x, qw, w1, B);
    k_conv2<<<(B + 3) / 4, 128>>>(w2, g1, be1, B);
    k_fc<<<(B + 15) / 16, 512>>>(g2, be2, fcw, fcb, out, B);
}